// round 11
// baseline (speedup 1.0000x reference)
#include <cuda_runtime.h>
#include <cuda_bf16.h>
#include <stdint.h>
#include <math.h>

#define B_  8
#define S_  1024
#define D_  1024
#define H_  16
#define DH_ 64
#define M_  (B_*S_)     // 8192

// Projected split planes
__device__ __nv_bfloat16 g_qh[(size_t)M_*D_], g_ql[(size_t)M_*D_];
__device__ __nv_bfloat16 g_kh[(size_t)M_*D_], g_kl[(size_t)M_*D_];
__device__ __nv_bfloat16 g_vh[(size_t)M_*D_], g_vl[(size_t)M_*D_];
__device__ __nv_bfloat16 g_ch[(size_t)M_*D_], g_cl[(size_t)M_*D_];
// Raw-input split planes
__device__ __nv_bfloat16 g_rqh[(size_t)M_*D_], g_rql[(size_t)M_*D_];
__device__ __nv_bfloat16 g_rkh[(size_t)M_*D_], g_rkl[(size_t)M_*D_];
__device__ __nv_bfloat16 g_rvh[(size_t)M_*D_], g_rvl[(size_t)M_*D_];
// Weight split planes (wq, wk, wv, wo)
__device__ __nv_bfloat16 g_wh[4][(size_t)D_*D_], g_wl[4][(size_t)D_*D_];
// Softmax partials: per (bh, row) x 16 column-ranges (8 bcol-blocks x 2 warp-halves)
__device__ float g_pmax[(size_t)128*1024*16];
__device__ float g_psum[(size_t)128*1024*16];

// ---------------------------------------------------------------------------
__device__ __forceinline__ uint32_t cvta_s(const void* p) {
    return (uint32_t)__cvta_generic_to_shared(p);
}
__device__ __forceinline__ void cpa16(uint32_t dst, const void* src) {
    asm volatile("cp.async.cg.shared.global [%0], [%1], 16;" :: "r"(dst), "l"(src));
}
__device__ __forceinline__ void ldsm4(uint32_t r[4], uint32_t a) {
    asm volatile("ldmatrix.sync.aligned.m8n8.x4.shared.b16 {%0,%1,%2,%3}, [%4];"
        : "=r"(r[0]), "=r"(r[1]), "=r"(r[2]), "=r"(r[3]) : "r"(a));
}
__device__ __forceinline__ void ldsm4t(uint32_t r[4], uint32_t a) {
    asm volatile("ldmatrix.sync.aligned.m8n8.x4.trans.shared.b16 {%0,%1,%2,%3}, [%4];"
        : "=r"(r[0]), "=r"(r[1]), "=r"(r[2]), "=r"(r[3]) : "r"(a));
}
__device__ __forceinline__ void mma_bf(float c[4], const uint32_t a[4],
                                       uint32_t b0, uint32_t b1) {
    asm volatile("mma.sync.aligned.m16n8k16.row.col.f32.bf16.bf16.f32 "
        "{%0,%1,%2,%3},{%4,%5,%6,%7},{%8,%9},{%0,%1,%2,%3};"
        : "+f"(c[0]), "+f"(c[1]), "+f"(c[2]), "+f"(c[3])
        : "r"(a[0]), "r"(a[1]), "r"(a[2]), "r"(a[3]), "r"(b0), "r"(b1));
}
__device__ __forceinline__ void split_bf(float x, __nv_bfloat16& h, __nv_bfloat16& l) {
    h = __float2bfloat16(x);
    l = __float2bfloat16(x - __bfloat162float(h));
}

// ---------------------------------------------------------------------------
// Pre-split: fp32 -> bf16 hi/lo planes
// ---------------------------------------------------------------------------
__global__ void __launch_bounds__(256)
split_kernel(const float* __restrict__ in, __nv_bfloat16* __restrict__ hi,
             __nv_bfloat16* __restrict__ lo, int n4)
{
    int i = blockIdx.x * blockDim.x + threadIdx.x;
    if (i >= n4) return;
    float4 v = ((const float4*)in)[i];
    __nv_bfloat16 h0,l0,h1,l1,h2,l2,h3,l3;
    split_bf(v.x,h0,l0); split_bf(v.y,h1,l1);
    split_bf(v.z,h2,l2); split_bf(v.w,h3,l3);
    ((__nv_bfloat162*)hi)[2*i]   = __halves2bfloat162(h0,h1);
    ((__nv_bfloat162*)hi)[2*i+1] = __halves2bfloat162(h2,h3);
    ((__nv_bfloat162*)lo)[2*i]   = __halves2bfloat162(l0,l1);
    ((__nv_bfloat162*)lo)[2*i+1] = __halves2bfloat162(l2,l3);
}

// ---------------------------------------------------------------------------
// Big GEMM v3 (round-8 WIN): 128 threads, 4 warps, warp tile 64x64.
// ---------------------------------------------------------------------------
#define STG_ 18944
template<bool DO_BN, bool SPLIT_OUT>
__global__ void __launch_bounds__(128, 2)
gemm_tc3(const __nv_bfloat16* __restrict__ Ah, const __nv_bfloat16* __restrict__ Al,
         const __nv_bfloat16* __restrict__ Wh, const __nv_bfloat16* __restrict__ Wl,
         const float* __restrict__ bias,
         const float* __restrict__ gam, const float* __restrict__ bet,
         const float* __restrict__ mmean, const float* __restrict__ mvar,
         float* __restrict__ Cf,
         __nv_bfloat16* __restrict__ Chg, __nv_bfloat16* __restrict__ Clg)
{
    extern __shared__ __align__(16) __nv_bfloat16 sm2[];
    const int tid = threadIdx.x, lane = tid & 31, warp = tid >> 5;
    const int brow = blockIdx.y * 128, bcol = blockIdx.x * 128;

    auto issue = [&](int slab, int buf) {
        __nv_bfloat16* st = sm2 + buf * STG_;
        const int ks = slab * 32;
        #pragma unroll
        for (int p = 0; p < 4; p++) {
            int c = tid + 128 * p;
            int r = c >> 2, q = (c & 3) * 8;
            const size_t ga = (size_t)(brow + r) * D_ + ks + q;
            cpa16(cvta_s(&st[r*40 + q]),        &Ah[ga]);
            cpa16(cvta_s(&st[5120 + r*40 + q]), &Al[ga]);
        }
        #pragma unroll
        for (int p = 0; p < 4; p++) {
            int c = tid + 128 * p;
            int r = c >> 4, q = (c & 15) * 8;
            const size_t gb = (size_t)(ks + r) * D_ + bcol + q;
            cpa16(cvta_s(&st[10240 + r*136 + q]), &Wh[gb]);
            cpa16(cvta_s(&st[14592 + r*136 + q]), &Wl[gb]);
        }
        asm volatile("cp.async.commit_group;");
    };

    const int wm = warp >> 1, wn = warp & 1;
    const int m0 = wm * 64, n0 = wn * 64;

    float acc[4][8][4];
    #pragma unroll
    for (int i = 0; i < 4; i++)
        #pragma unroll
        for (int j = 0; j < 8; j++)
            #pragma unroll
            for (int q = 0; q < 4; q++) acc[i][j][q] = 0.f;

    issue(0, 0);
    for (int s = 0; s < 32; s++) {
        const int buf = s & 1;
        if (s + 1 < 32) {
            issue(s + 1, buf ^ 1);
            asm volatile("cp.async.wait_group 1;");
        } else {
            asm volatile("cp.async.wait_group 0;");
        }
        __syncthreads();

        const __nv_bfloat16* sAh = sm2 + buf * STG_;
        const __nv_bfloat16* sAl = sAh + 5120;
        const __nv_bfloat16* sBh = sAh + 10240;
        const __nv_bfloat16* sBl = sAh + 14592;

        #pragma unroll
        for (int kk = 0; kk < 32; kk += 16) {
            uint32_t ah[4][4], al[4][4];
            #pragma unroll
            for (int mi = 0; mi < 4; mi++) {
                int off = (m0 + mi*16 + (lane & 15)) * 40 + kk + ((lane >> 4) << 3);
                ldsm4(ah[mi], cvta_s(&sAh[off]));
                ldsm4(al[mi], cvta_s(&sAl[off]));
            }
            #pragma unroll
            for (int nj = 0; nj < 4; nj++) {
                uint32_t bh[4], bl[4];
                int off = (kk + (lane & 15)) * 136 + n0 + nj*16 + ((lane >> 4) << 3);
                ldsm4t(bh, cvta_s(&sBh[off]));
                ldsm4t(bl, cvta_s(&sBl[off]));
                #pragma unroll
                for (int mi = 0; mi < 4; mi++) {
                    mma_bf(acc[mi][2*nj],   ah[mi], bh[0], bh[1]);
                    mma_bf(acc[mi][2*nj],   ah[mi], bl[0], bl[1]);
                    mma_bf(acc[mi][2*nj],   al[mi], bh[0], bh[1]);
                    mma_bf(acc[mi][2*nj+1], ah[mi], bh[2], bh[3]);
                    mma_bf(acc[mi][2*nj+1], ah[mi], bl[2], bl[3]);
                    mma_bf(acc[mi][2*nj+1], al[mi], bh[2], bh[3]);
                }
            }
        }
        __syncthreads();
    }

    #pragma unroll
    for (int mi = 0; mi < 4; mi++) {
        int r0 = brow + m0 + mi*16 + (lane >> 2);
        #pragma unroll
        for (int nj = 0; nj < 8; nj++) {
            int c = bcol + n0 + nj*8 + (lane & 3)*2;
            float b0v = bias[c], b1v = bias[c+1];
            float sc0 = 1.f, sh0 = 0.f, sc1 = 1.f, sh1 = 0.f;
            if (DO_BN) {
                sc0 = gam[c]   * rsqrtf(mvar[c]   + 1e-3f); sh0 = bet[c]   - mmean[c]   * sc0;
                sc1 = gam[c+1] * rsqrtf(mvar[c+1] + 1e-3f); sh1 = bet[c+1] - mmean[c+1] * sc1;
            }
            float y00 = fmaxf(acc[mi][nj][0] + b0v, 0.f);
            float y01 = fmaxf(acc[mi][nj][1] + b1v, 0.f);
            float y10 = fmaxf(acc[mi][nj][2] + b0v, 0.f);
            float y11 = fmaxf(acc[mi][nj][3] + b1v, 0.f);
            if (DO_BN) {
                y00 = y00*sc0 + sh0; y01 = y01*sc1 + sh1;
                y10 = y10*sc0 + sh0; y11 = y11*sc1 + sh1;
            }
            if constexpr (SPLIT_OUT) {
                __nv_bfloat16 h0,l0,h1,l1,h2,l2,h3,l3;
                split_bf(y00,h0,l0); split_bf(y01,h1,l1);
                split_bf(y10,h2,l2); split_bf(y11,h3,l3);
                *(__nv_bfloat162*)&Chg[(size_t)r0*D_ + c]     = __halves2bfloat162(h0,h1);
                *(__nv_bfloat162*)&Clg[(size_t)r0*D_ + c]     = __halves2bfloat162(l0,l1);
                *(__nv_bfloat162*)&Chg[(size_t)(r0+8)*D_ + c] = __halves2bfloat162(h2,h3);
                *(__nv_bfloat162*)&Clg[(size_t)(r0+8)*D_ + c] = __halves2bfloat162(l2,l3);
            } else {
                *(float2*)&Cf[(size_t)r0*D_ + c]     = make_float2(y00, y01);
                *(float2*)&Cf[(size_t)(r0+8)*D_ + c] = make_float2(y10, y11);
            }
        }
    }
}

// ---------------------------------------------------------------------------
// scores v2: 128 threads, 4 warps, warp tile 64x64 (MMA:ldsm = 6).
// Writes raw (scaled+masked) scores to attn, and per (row, 64-col range)
// partial max / sum-of-exp into g_pmax/g_psum[bh][row][bcolblk*2 + wn].
// ---------------------------------------------------------------------------
__global__ void __launch_bounds__(128, 2)
scores_tc(const float* __restrict__ mask, float* __restrict__ attn)
{
    extern __shared__ __align__(16) __nv_bfloat16 sm[];
    __nv_bfloat16* sQh = sm;
    __nv_bfloat16* sQl = sm + 9216;
    __nv_bfloat16* sKh = sm + 18432;
    __nv_bfloat16* sKl = sm + 27648;

    const int bh = blockIdx.z, b = bh >> 4, h = bh & 15;
    const size_t base = (size_t)b * S_ * D_ + h * DH_;
    const int tid = threadIdx.x, lane = tid & 31, warp = tid >> 5;
    const int brow = blockIdx.y * 128, bcol = blockIdx.x * 128;

    #pragma unroll
    for (int p = 0; p < 8; p++) {
        int idx = tid + 128 * p;          // 0..1023
        int row = idx >> 3;
        int ch  = (idx & 7) * 8;
        *(uint4*)&sQh[row*72 + ch] = *(const uint4*)&g_qh[base + (size_t)(brow + row)*D_ + ch];
        *(uint4*)&sQl[row*72 + ch] = *(const uint4*)&g_ql[base + (size_t)(brow + row)*D_ + ch];
        *(uint4*)&sKh[row*72 + ch] = *(const uint4*)&g_kh[base + (size_t)(bcol + row)*D_ + ch];
        *(uint4*)&sKl[row*72 + ch] = *(const uint4*)&g_kl[base + (size_t)(bcol + row)*D_ + ch];
    }
    __syncthreads();

    const int wm = warp >> 1, wn = warp & 1;
    const int m0 = wm * 64, n0 = wn * 64;

    float acc[4][8][4];
    #pragma unroll
    for (int i = 0; i < 4; i++)
        #pragma unroll
        for (int j = 0; j < 8; j++)
            #pragma unroll
            for (int q = 0; q < 4; q++) acc[i][j][q] = 0.f;

    #pragma unroll
    for (int kk = 0; kk < 64; kk += 16) {
        uint32_t ah[4][4], al[4][4];
        #pragma unroll
        for (int mi = 0; mi < 4; mi++) {
            int off = (m0 + mi*16 + (lane & 15)) * 72 + kk + ((lane >> 4) << 3);
            ldsm4(ah[mi], cvta_s(&sQh[off]));
            ldsm4(al[mi], cvta_s(&sQl[off]));
        }
        #pragma unroll
        for (int nj = 0; nj < 4; nj++) {
            int nr = n0 + nj*16 + ((lane & 7) | (((lane >> 4) & 1) << 3));
            int off = nr * 72 + kk + (((lane >> 3) & 1) << 3);
            uint32_t bh4[4], bl4[4];
            ldsm4(bh4, cvta_s(&sKh[off]));
            ldsm4(bl4, cvta_s(&sKl[off]));
            #pragma unroll
            for (int mi = 0; mi < 4; mi++) {
                mma_bf(acc[mi][2*nj],   ah[mi], bh4[0], bh4[1]);
                mma_bf(acc[mi][2*nj],   ah[mi], bl4[0], bl4[1]);
                mma_bf(acc[mi][2*nj],   al[mi], bh4[0], bh4[1]);
                mma_bf(acc[mi][2*nj+1], ah[mi], bh4[2], bh4[3]);
                mma_bf(acc[mi][2*nj+1], ah[mi], bl4[2], bl4[3]);
                mma_bf(acc[mi][2*nj+1], al[mi], bh4[2], bh4[3]);
            }
        }
    }

    // mask values (cached in regs)
    float mk0[8], mk1[8];
    #pragma unroll
    for (int nj = 0; nj < 8; nj++) {
        int c = bcol + n0 + nj*8 + (lane & 3)*2;
        mk0[nj] = mask[b*S_ + c]     * (-1e9f);
        mk1[nj] = mask[b*S_ + c + 1] * (-1e9f);
    }

    float* outp = attn + (size_t)bh * S_ * S_;
    const int pidx = blockIdx.x * 2 + wn;
    #pragma unroll
    for (int mi = 0; mi < 4; mi++) {
        int r0 = brow + m0 + mi*16 + (lane >> 2);
        float mA = -3.4e38f, mB = -3.4e38f;
        #pragma unroll
        for (int nj = 0; nj < 8; nj++) {
            int c = bcol + n0 + nj*8 + (lane & 3)*2;
            float x0 = fmaf(acc[mi][nj][0], 0.125f, mk0[nj]);
            float x1 = fmaf(acc[mi][nj][1], 0.125f, mk1[nj]);
            float x2 = fmaf(acc[mi][nj][2], 0.125f, mk0[nj]);
            float x3 = fmaf(acc[mi][nj][3], 0.125f, mk1[nj]);
            acc[mi][nj][0] = x0; acc[mi][nj][1] = x1;
            acc[mi][nj][2] = x2; acc[mi][nj][3] = x3;
            *(float2*)&outp[(size_t)r0*S_ + c]     = make_float2(x0, x1);
            *(float2*)&outp[(size_t)(r0+8)*S_ + c] = make_float2(x2, x3);
            mA = fmaxf(mA, fmaxf(x0, x1));
            mB = fmaxf(mB, fmaxf(x2, x3));
        }
        #pragma unroll
        for (int o = 1; o < 4; o <<= 1) {
            mA = fmaxf(mA, __shfl_xor_sync(0xffffffffu, mA, o));
            mB = fmaxf(mB, __shfl_xor_sync(0xffffffffu, mB, o));
        }
        float sA = 0.f, sB = 0.f;
        #pragma unroll
        for (int nj = 0; nj < 8; nj++) {
            sA += __expf(acc[mi][nj][0] - mA) + __expf(acc[mi][nj][1] - mA);
            sB += __expf(acc[mi][nj][2] - mB) + __expf(acc[mi][nj][3] - mB);
        }
        #pragma unroll
        for (int o = 1; o < 4; o <<= 1) {
            sA += __shfl_xor_sync(0xffffffffu, sA, o);
            sB += __shfl_xor_sync(0xffffffffu, sB, o);
        }
        if ((lane & 3) == 0) {
            size_t pa = ((size_t)bh*1024 + r0)*16 + pidx;
            size_t pb = ((size_t)bh*1024 + r0 + 8)*16 + pidx;
            g_pmax[pa] = mA; g_psum[pa] = sA;
            g_pmax[pb] = mB; g_psum[pb] = sB;
        }
    }
}

// ---------------------------------------------------------------------------
// pv_fused = softmax + ctx: combines partials, normalizes raw scores in place
// (writing the final attn output), and computes ctx = P @ V -> split planes.
// ---------------------------------------------------------------------------
__global__ void __launch_bounds__(256)
pv_fused(float* __restrict__ attn)
{
    __shared__ __align__(16) __nv_bfloat16 sAh[128*40], sAl[128*40];
    __shared__ __align__(16) __nv_bfloat16 sBh[32*72],  sBl[32*72];
    __shared__ float sMx[128], sInv[128];

    const int bh = blockIdx.y, b = bh >> 4, h = bh & 15;
    float* A = attn + (size_t)bh * S_ * S_;
    const __nv_bfloat16* Vh = g_vh + (size_t)b * S_ * D_ + h * DH_;
    const __nv_bfloat16* Vl = g_vl + (size_t)b * S_ * D_ + h * DH_;

    const int tid = threadIdx.x, lane = tid & 31, warp = tid >> 5;
    const int brow = blockIdx.x * 128;

    if (tid < 128) {
        size_t pb = ((size_t)bh*1024 + brow + tid) * 16;
        float pm[16], ps[16];
        #pragma unroll
        for (int j = 0; j < 4; j++) {
            *(float4*)&pm[j*4] = *(const float4*)&g_pmax[pb + j*4];
            *(float4*)&ps[j*4] = *(const float4*)&g_psum[pb + j*4];
        }
        float mx = pm[0];
        #pragma unroll
        for (int j = 1; j < 16; j++) mx = fmaxf(mx, pm[j]);
        float s = 0.f;
        #pragma unroll
        for (int j = 0; j < 16; j++) s += ps[j] * __expf(pm[j] - mx);
        sMx[tid] = mx; sInv[tid] = 1.f / s;
    }
    __syncthreads();

    float4 stA[4]; uint4 stB[2];
    auto loadG = [&](int ks) {
        #pragma unroll
        for (int p = 0; p < 4; p++) {
            int row = (tid >> 3) + 32 * p, col = (tid & 7) * 4;
            stA[p] = *(const float4*)&A[(size_t)(brow + row) * S_ + ks + col];
        }
        #pragma unroll
        for (int p = 0; p < 2; p++) {
            int idx = tid + 256 * p;
            int r  = (idx & 255) >> 3;
            int ch = (idx & 7) * 8;
            const __nv_bfloat16* src = (idx < 256) ? Vh : Vl;
            stB[p] = *(const uint4*)&src[(size_t)(ks + r) * D_ + ch];
        }
    };
    auto storeS = [&](int ks) {
        #pragma unroll
        for (int p = 0; p < 4; p++) {
            int row = (tid >> 3) + 32 * p, col = (tid & 7) * 4;
            const float mx = sMx[row], inv = sInv[row];
            float v[4] = {stA[p].x, stA[p].y, stA[p].z, stA[p].w};
            #pragma unroll
            for (int i = 0; i < 4; i++) v[i] = __expf(v[i] - mx) * inv;
            *(float4*)&A[(size_t)(brow + row) * S_ + ks + col] =
                make_float4(v[0], v[1], v[2], v[3]);
            __nv_bfloat16 hh[4], ll[4];
            #pragma unroll
            for (int i = 0; i < 4; i++) split_bf(v[i], hh[i], ll[i]);
            *(__nv_bfloat162*)&sAh[row*40 + col]     = __halves2bfloat162(hh[0], hh[1]);
            *(__nv_bfloat162*)&sAh[row*40 + col + 2] = __halves2bfloat162(hh[2], hh[3]);
            *(__nv_bfloat162*)&sAl[row*40 + col]     = __halves2bfloat162(ll[0], ll[1]);
            *(__nv_bfloat162*)&sAl[row*40 + col + 2] = __halves2bfloat162(ll[2], ll[3]);
        }
        #pragma unroll
        for (int p = 0; p < 2; p++) {
            int idx = tid + 256 * p;
            int r  = (idx & 255) >> 3;
            int ch = (idx & 7) * 8;
            __nv_bfloat16* dst = (idx < 256) ? sBh : sBl;
            *(uint4*)&dst[r*72 + ch] = stB[p];
        }
    };

    const int wm = warp >> 1, wn = warp & 1;
    const int m0 = wm * 32, n0 = wn * 32;

    float acc[2][4][4];
    #pragma unroll
    for (int i = 0; i < 2; i++)
        #pragma unroll
        for (int j = 0; j < 4; j++)
            #pragma unroll
            for (int q = 0; q < 4; q++) acc[i][j][q] = 0.f;

    loadG(0);
    for (int ks = 0; ks < S_; ks += 32) {
        storeS(ks);
        __syncthreads();
        if (ks + 32 < S_) loadG(ks + 32);

        #pragma unroll
        for (int kk = 0; kk < 32; kk += 16) {
            uint32_t ah[2][4], al[2][4];
            #pragma unroll
            for (int mi = 0; mi < 2; mi++) {
                int off = (m0 + mi*16 + (lane & 15)) * 40 + kk + ((lane >> 4) << 3);
                ldsm4(ah[mi], cvta_s(&sAh[off]));
                ldsm4(al[mi], cvta_s(&sAl[off]));
            }
            #pragma unroll
            for (int nj = 0; nj < 2; nj++) {
                uint32_t bh4[4], bl4[4];
                int off = (kk + (lane & 15)) * 72 + n0 + nj*16 + ((lane >> 4) << 3);
                ldsm4t(bh4, cvta_s(&sBh[off]));
                ldsm4t(bl4, cvta_s(&sBl[off]));
                #pragma unroll
                for (int mi = 0; mi < 2; mi++) {
                    mma_bf(acc[mi][2*nj],   ah[mi], bh4[0], bh4[1]);
                    mma_bf(acc[mi][2*nj],   ah[mi], bl4[0], bl4[1]);
                    mma_bf(acc[mi][2*nj],   al[mi], bh4[0], bh4[1]);
                    mma_bf(acc[mi][2*nj+1], ah[mi], bh4[2], bh4[3]);
                    mma_bf(acc[mi][2*nj+1], ah[mi], bl4[2], bl4[3]);
                    mma_bf(acc[mi][2*nj+1], al[mi], bh4[2], bh4[3]);
                }
            }
        }
        __syncthreads();
    }

    __nv_bfloat16* Ch = g_ch + (size_t)b * S_ * D_ + h * DH_;
    __nv_bfloat16* Cl = g_cl + (size_t)b * S_ * D_ + h * DH_;
    #pragma unroll
    for (int mi = 0; mi < 2; mi++) {
        int r0 = brow + m0 + mi*16 + (lane >> 2);
        #pragma unroll
        for (int nj = 0; nj < 4; nj++) {
            int c = n0 + nj*8 + (lane & 3)*2;
            __nv_bfloat16 h0,l0,h1,l1,h2,l2,h3,l3;
            split_bf(acc[mi][nj][0], h0, l0); split_bf(acc[mi][nj][1], h1, l1);
            split_bf(acc[mi][nj][2], h2, l2); split_bf(acc[mi][nj][3], h3, l3);
            *(__nv_bfloat162*)&Ch[(size_t)r0*D_ + c]     = __halves2bfloat162(h0, h1);
            *(__nv_bfloat162*)&Cl[(size_t)r0*D_ + c]     = __halves2bfloat162(l0, l1);
            *(__nv_bfloat162*)&Ch[(size_t)(r0+8)*D_ + c] = __halves2bfloat162(h2, h3);
            *(__nv_bfloat162*)&Cl[(size_t)(r0+8)*D_ + c] = __halves2bfloat162(l2, l3);
        }
    }
}

// ---------------------------------------------------------------------------
extern "C" void kernel_launch(void* const* d_in, const int* in_sizes, int n_in,
                              void* d_out, int out_size)
{
    const float* q    = (const float*)d_in[0];
    const float* k    = (const float*)d_in[1];
    const float* v    = (const float*)d_in[2];
    const float* mask = (const float*)d_in[3];
    const float* wq = (const float*)d_in[4];  const float* bq = (const float*)d_in[5];
    const float* wk = (const float*)d_in[6];  const float* bk = (const float*)d_in[7];
    const float* wv = (const float*)d_in[8];  const float* bv = (const float*)d_in[9];
    const float* wo = (const float*)d_in[10]; const float* bo = (const float*)d_in[11];
    const float* g1 = (const float*)d_in[12]; const float* be1 = (const float*)d_in[13];
    const float* mm1 = (const float*)d_in[14]; const float* mv1 = (const float*)d_in[15];
    const float* g2 = (const float*)d_in[16]; const float* be2 = (const float*)d_in[17];
    const float* mm2 = (const float*)d_in[18]; const float* mv2 = (const float*)d_in[19];
    const float* g3 = (const float*)d_in[20]; const float* be3 = (const float*)d_in[21];
    const float* mm3 = (const float*)d_in[22]; const float* mv3 = (const float*)d_in[23];

    float* out  = (float*)d_out;
    float* attn = out + (size_t)M_ * D_;

    void* p;
    __nv_bfloat16 *qh,*ql,*kh,*kl,*vh,*vl,*ch,*cl;
    __nv_bfloat16 *rqh,*rql,*rkh,*rkl,*rvh,*rvl,*wph,*wpl;
    cudaGetSymbolAddress(&p, g_qh); qh = (__nv_bfloat16*)p;
    cudaGetSymbolAddress(&p, g_ql); ql = (__nv_bfloat16*)p;
    cudaGetSymbolAddress(&p, g_kh); kh = (__nv_bfloat16*)p;
    cudaGetSymbolAddress(&p, g_kl); kl = (__nv_bfloat16*)p;
    cudaGetSymbolAddress(&p, g_vh); vh = (__nv_bfloat16*)p;
    cudaGetSymbolAddress(&p, g_vl); vl = (__nv_bfloat16*)p;
    cudaGetSymbolAddress(&p, g_ch); ch = (__nv_bfloat16*)p;
    cudaGetSymbolAddress(&p, g_cl); cl = (__nv_bfloat16*)p;
    cudaGetSymbolAddress(&p, g_rqh); rqh = (__nv_bfloat16*)p;
    cudaGetSymbolAddress(&p, g_rql); rql = (__nv_bfloat16*)p;
    cudaGetSymbolAddress(&p, g_rkh); rkh = (__nv_bfloat16*)p;
    cudaGetSymbolAddress(&p, g_rkl); rkl = (__nv_bfloat16*)p;
    cudaGetSymbolAddress(&p, g_rvh); rvh = (__nv_bfloat16*)p;
    cudaGetSymbolAddress(&p, g_rvl); rvl = (__nv_bfloat16*)p;
    cudaGetSymbolAddress(&p, g_wh); wph = (__nv_bfloat16*)p;
    cudaGetSymbolAddress(&p, g_wl); wpl = (__nv_bfloat16*)p;

    const size_t WSZ = (size_t)D_ * D_;
    const int n4a = (int)((size_t)M_ * D_ / 4);
    const int n4w = (int)(WSZ / 4);

    split_kernel<<<n4a/256, 256>>>(q, rqh, rql, n4a);
    split_kernel<<<n4a/256, 256>>>(k, rkh, rkl, n4a);
    split_kernel<<<n4a/256, 256>>>(v, rvh, rvl, n4a);
    split_kernel<<<n4w/256, 256>>>(wq, wph + 0*WSZ, wpl + 0*WSZ, n4w);
    split_kernel<<<n4w/256, 256>>>(wk, wph + 1*WSZ, wpl + 1*WSZ, n4w);
    split_kernel<<<n4w/256, 256>>>(wv, wph + 2*WSZ, wpl + 2*WSZ, n4w);
    split_kernel<<<n4w/256, 256>>>(wo, wph + 3*WSZ, wpl + 3*WSZ, n4w);

    cudaFuncSetAttribute(gemm_tc3<true,true>,
        cudaFuncAttributeMaxDynamicSharedMemorySize, 2*STG_*2);
    cudaFuncSetAttribute(gemm_tc3<false,false>,
        cudaFuncAttributeMaxDynamicSharedMemorySize, 2*STG_*2);
    cudaFuncSetAttribute(scores_tc, cudaFuncAttributeMaxDynamicSharedMemorySize, 73728);

    dim3 gp(D_/128, M_/128);   // (8, 64)
    gemm_tc3<true,true><<<gp,128,2*STG_*2>>>(rqh, rql, wph + 0*WSZ, wpl + 0*WSZ,
        bq, g1, be1, mm1, mv1, nullptr, qh, ql);
    gemm_tc3<true,true><<<gp,128,2*STG_*2>>>(rkh, rkl, wph + 1*WSZ, wpl + 1*WSZ,
        bk, g2, be2, mm2, mv2, nullptr, kh, kl);
    gemm_tc3<true,true><<<gp,128,2*STG_*2>>>(rvh, rvl, wph + 2*WSZ, wpl + 2*WSZ,
        bv, g3, be3, mm3, mv3, nullptr, vh, vl);

    scores_tc<<<dim3(8,8,128),128,73728>>>(mask, attn);

    pv_fused<<<dim3(8,128),256>>>(attn);

    gemm_tc3<false,false><<<gp,128,2*STG_*2>>>(ch, cl, wph + 3*WSZ, wpl + 3*WSZ,
        bo, nullptr, nullptr, nullptr, nullptr, out, nullptr, nullptr);
}

// round 12
// speedup vs baseline: 1.0967x; 1.0967x over previous
#include <cuda_runtime.h>
#include <cuda_bf16.h>
#include <stdint.h>
#include <math.h>

#define B_  8
#define S_  1024
#define D_  1024
#define H_  16
#define DH_ 64
#define M_  (B_*S_)     // 8192

// Projected split planes
__device__ __nv_bfloat16 g_qh[(size_t)M_*D_], g_ql[(size_t)M_*D_];
__device__ __nv_bfloat16 g_kh[(size_t)M_*D_], g_kl[(size_t)M_*D_];
__device__ __nv_bfloat16 g_vh[(size_t)M_*D_], g_vl[(size_t)M_*D_];
__device__ __nv_bfloat16 g_ch[(size_t)M_*D_], g_cl[(size_t)M_*D_];
// Raw-input split planes
__device__ __nv_bfloat16 g_rqh[(size_t)M_*D_], g_rql[(size_t)M_*D_];
__device__ __nv_bfloat16 g_rkh[(size_t)M_*D_], g_rkl[(size_t)M_*D_];
__device__ __nv_bfloat16 g_rvh[(size_t)M_*D_], g_rvl[(size_t)M_*D_];
// Weight split planes (wq, wk, wv, wo)
__device__ __nv_bfloat16 g_wh[4][(size_t)D_*D_], g_wl[4][(size_t)D_*D_];
// Softmax partials: per (bh, row) x 16 column-ranges (8 bcol-blocks x 2 warp-halves)
__device__ float g_pmax[(size_t)128*1024*16];
__device__ float g_psum[(size_t)128*1024*16];

// ---------------------------------------------------------------------------
__device__ __forceinline__ uint32_t cvta_s(const void* p) {
    return (uint32_t)__cvta_generic_to_shared(p);
}
__device__ __forceinline__ void cpa16(uint32_t dst, const void* src) {
    asm volatile("cp.async.cg.shared.global [%0], [%1], 16;" :: "r"(dst), "l"(src));
}
__device__ __forceinline__ void ldsm4(uint32_t r[4], uint32_t a) {
    asm volatile("ldmatrix.sync.aligned.m8n8.x4.shared.b16 {%0,%1,%2,%3}, [%4];"
        : "=r"(r[0]), "=r"(r[1]), "=r"(r[2]), "=r"(r[3]) : "r"(a));
}
__device__ __forceinline__ void ldsm4t(uint32_t r[4], uint32_t a) {
    asm volatile("ldmatrix.sync.aligned.m8n8.x4.trans.shared.b16 {%0,%1,%2,%3}, [%4];"
        : "=r"(r[0]), "=r"(r[1]), "=r"(r[2]), "=r"(r[3]) : "r"(a));
}
__device__ __forceinline__ void mma_bf(float c[4], const uint32_t a[4],
                                       uint32_t b0, uint32_t b1) {
    asm volatile("mma.sync.aligned.m16n8k16.row.col.f32.bf16.bf16.f32 "
        "{%0,%1,%2,%3},{%4,%5,%6,%7},{%8,%9},{%0,%1,%2,%3};"
        : "+f"(c[0]), "+f"(c[1]), "+f"(c[2]), "+f"(c[3])
        : "r"(a[0]), "r"(a[1]), "r"(a[2]), "r"(a[3]), "r"(b0), "r"(b1));
}
__device__ __forceinline__ void split_bf(float x, __nv_bfloat16& h, __nv_bfloat16& l) {
    h = __float2bfloat16(x);
    l = __float2bfloat16(x - __bfloat162float(h));
}

// ---------------------------------------------------------------------------
// Pre-split: fp32 -> bf16 hi/lo planes
// ---------------------------------------------------------------------------
__global__ void __launch_bounds__(256)
split_kernel(const float* __restrict__ in, __nv_bfloat16* __restrict__ hi,
             __nv_bfloat16* __restrict__ lo, int n4)
{
    int i = blockIdx.x * blockDim.x + threadIdx.x;
    if (i >= n4) return;
    float4 v = ((const float4*)in)[i];
    __nv_bfloat16 h0,l0,h1,l1,h2,l2,h3,l3;
    split_bf(v.x,h0,l0); split_bf(v.y,h1,l1);
    split_bf(v.z,h2,l2); split_bf(v.w,h3,l3);
    ((__nv_bfloat162*)hi)[2*i]   = __halves2bfloat162(h0,h1);
    ((__nv_bfloat162*)hi)[2*i+1] = __halves2bfloat162(h2,h3);
    ((__nv_bfloat162*)lo)[2*i]   = __halves2bfloat162(l0,l1);
    ((__nv_bfloat162*)lo)[2*i+1] = __halves2bfloat162(l2,l3);
}

// ---------------------------------------------------------------------------
// Big GEMM v4: 128 threads, 4 warps, warp tile 64x64, THREE-stage cp.async.
// smem: 3 stages x STG_ elems (Ah@0, Al@5120, Bh@10240, Bl@14592 per stage).
// ---------------------------------------------------------------------------
#define STG_ 18944
template<bool DO_BN, bool SPLIT_OUT>
__global__ void __launch_bounds__(128, 2)
gemm_tc3(const __nv_bfloat16* __restrict__ Ah, const __nv_bfloat16* __restrict__ Al,
         const __nv_bfloat16* __restrict__ Wh, const __nv_bfloat16* __restrict__ Wl,
         const float* __restrict__ bias,
         const float* __restrict__ gam, const float* __restrict__ bet,
         const float* __restrict__ mmean, const float* __restrict__ mvar,
         float* __restrict__ Cf,
         __nv_bfloat16* __restrict__ Chg, __nv_bfloat16* __restrict__ Clg)
{
    extern __shared__ __align__(16) __nv_bfloat16 sm2[];
    const int tid = threadIdx.x, lane = tid & 31, warp = tid >> 5;
    const int brow = blockIdx.y * 128, bcol = blockIdx.x * 128;

    auto issue = [&](int slab, int buf) {
        __nv_bfloat16* st = sm2 + buf * STG_;
        const int ks = slab * 32;
        #pragma unroll
        for (int p = 0; p < 4; p++) {
            int c = tid + 128 * p;
            int r = c >> 2, q = (c & 3) * 8;
            const size_t ga = (size_t)(brow + r) * D_ + ks + q;
            cpa16(cvta_s(&st[r*40 + q]),        &Ah[ga]);
            cpa16(cvta_s(&st[5120 + r*40 + q]), &Al[ga]);
        }
        #pragma unroll
        for (int p = 0; p < 4; p++) {
            int c = tid + 128 * p;
            int r = c >> 4, q = (c & 15) * 8;
            const size_t gb = (size_t)(ks + r) * D_ + bcol + q;
            cpa16(cvta_s(&st[10240 + r*136 + q]), &Wh[gb]);
            cpa16(cvta_s(&st[14592 + r*136 + q]), &Wl[gb]);
        }
        asm volatile("cp.async.commit_group;");
    };

    const int wm = warp >> 1, wn = warp & 1;
    const int m0 = wm * 64, n0 = wn * 64;

    float acc[4][8][4];
    #pragma unroll
    for (int i = 0; i < 4; i++)
        #pragma unroll
        for (int j = 0; j < 8; j++)
            #pragma unroll
            for (int q = 0; q < 4; q++) acc[i][j][q] = 0.f;

    issue(0, 0);
    issue(1, 1);
    for (int s = 0; s < 32; s++) {
        if (s + 2 < 32) {
            issue(s + 2, (s + 2) % 3);
            asm volatile("cp.async.wait_group 2;");
        } else if (s + 1 < 32) {
            asm volatile("cp.async.wait_group 1;");
        } else {
            asm volatile("cp.async.wait_group 0;");
        }
        __syncthreads();

        const __nv_bfloat16* sAh = sm2 + (s % 3) * STG_;
        const __nv_bfloat16* sAl = sAh + 5120;
        const __nv_bfloat16* sBh = sAh + 10240;
        const __nv_bfloat16* sBl = sAh + 14592;

        #pragma unroll
        for (int kk = 0; kk < 32; kk += 16) {
            uint32_t ah[4][4], al[4][4];
            #pragma unroll
            for (int mi = 0; mi < 4; mi++) {
                int off = (m0 + mi*16 + (lane & 15)) * 40 + kk + ((lane >> 4) << 3);
                ldsm4(ah[mi], cvta_s(&sAh[off]));
                ldsm4(al[mi], cvta_s(&sAl[off]));
            }
            #pragma unroll
            for (int nj = 0; nj < 4; nj++) {
                uint32_t bh[4], bl[4];
                int off = (kk + (lane & 15)) * 136 + n0 + nj*16 + ((lane >> 4) << 3);
                ldsm4t(bh, cvta_s(&sBh[off]));
                ldsm4t(bl, cvta_s(&sBl[off]));
                #pragma unroll
                for (int mi = 0; mi < 4; mi++) {
                    mma_bf(acc[mi][2*nj],   ah[mi], bh[0], bh[1]);
                    mma_bf(acc[mi][2*nj],   ah[mi], bl[0], bl[1]);
                    mma_bf(acc[mi][2*nj],   al[mi], bh[0], bh[1]);
                    mma_bf(acc[mi][2*nj+1], ah[mi], bh[2], bh[3]);
                    mma_bf(acc[mi][2*nj+1], ah[mi], bl[2], bl[3]);
                    mma_bf(acc[mi][2*nj+1], al[mi], bh[2], bh[3]);
                }
            }
        }
        __syncthreads();
    }

    #pragma unroll
    for (int mi = 0; mi < 4; mi++) {
        int r0 = brow + m0 + mi*16 + (lane >> 2);
        #pragma unroll
        for (int nj = 0; nj < 8; nj++) {
            int c = bcol + n0 + nj*8 + (lane & 3)*2;
            float b0v = bias[c], b1v = bias[c+1];
            float sc0 = 1.f, sh0 = 0.f, sc1 = 1.f, sh1 = 0.f;
            if (DO_BN) {
                sc0 = gam[c]   * rsqrtf(mvar[c]   + 1e-3f); sh0 = bet[c]   - mmean[c]   * sc0;
                sc1 = gam[c+1] * rsqrtf(mvar[c+1] + 1e-3f); sh1 = bet[c+1] - mmean[c+1] * sc1;
            }
            float y00 = fmaxf(acc[mi][nj][0] + b0v, 0.f);
            float y01 = fmaxf(acc[mi][nj][1] + b1v, 0.f);
            float y10 = fmaxf(acc[mi][nj][2] + b0v, 0.f);
            float y11 = fmaxf(acc[mi][nj][3] + b1v, 0.f);
            if (DO_BN) {
                y00 = y00*sc0 + sh0; y01 = y01*sc1 + sh1;
                y10 = y10*sc0 + sh0; y11 = y11*sc1 + sh1;
            }
            if constexpr (SPLIT_OUT) {
                __nv_bfloat16 h0,l0,h1,l1,h2,l2,h3,l3;
                split_bf(y00,h0,l0); split_bf(y01,h1,l1);
                split_bf(y10,h2,l2); split_bf(y11,h3,l3);
                *(__nv_bfloat162*)&Chg[(size_t)r0*D_ + c]     = __halves2bfloat162(h0,h1);
                *(__nv_bfloat162*)&Clg[(size_t)r0*D_ + c]     = __halves2bfloat162(l0,l1);
                *(__nv_bfloat162*)&Chg[(size_t)(r0+8)*D_ + c] = __halves2bfloat162(h2,h3);
                *(__nv_bfloat162*)&Clg[(size_t)(r0+8)*D_ + c] = __halves2bfloat162(l2,l3);
            } else {
                *(float2*)&Cf[(size_t)r0*D_ + c]     = make_float2(y00, y01);
                *(float2*)&Cf[(size_t)(r0+8)*D_ + c] = make_float2(y10, y11);
            }
        }
    }
}

// ---------------------------------------------------------------------------
// scores (round-9 proven): 256 threads, 8 warps, warp tile 32x64.
// Writes raw (scaled+masked) scores to attn, and per (row, 64-col range)
// partial max / sum-of-exp into g_pmax/g_psum[bh][row][bcolblk*2 + wn].
// ---------------------------------------------------------------------------
__global__ void __launch_bounds__(256)
scores_tc(const float* __restrict__ mask, float* __restrict__ attn)
{
    extern __shared__ __align__(16) __nv_bfloat16 sm[];
    __nv_bfloat16* sQh = sm;
    __nv_bfloat16* sQl = sm + 9216;
    __nv_bfloat16* sKh = sm + 18432;
    __nv_bfloat16* sKl = sm + 27648;

    const int bh = blockIdx.z, b = bh >> 4, h = bh & 15;
    const size_t base = (size_t)b * S_ * D_ + h * DH_;
    const int tid = threadIdx.x, lane = tid & 31, warp = tid >> 5;
    const int brow = blockIdx.y * 128, bcol = blockIdx.x * 128;

    #pragma unroll
    for (int p = 0; p < 4; p++) {
        int idx = tid + 256 * p;
        int row = idx >> 3;
        int ch  = (idx & 7) * 8;
        *(uint4*)&sQh[row*72 + ch] = *(const uint4*)&g_qh[base + (size_t)(brow + row)*D_ + ch];
        *(uint4*)&sQl[row*72 + ch] = *(const uint4*)&g_ql[base + (size_t)(brow + row)*D_ + ch];
        *(uint4*)&sKh[row*72 + ch] = *(const uint4*)&g_kh[base + (size_t)(bcol + row)*D_ + ch];
        *(uint4*)&sKl[row*72 + ch] = *(const uint4*)&g_kl[base + (size_t)(bcol + row)*D_ + ch];
    }
    __syncthreads();

    const int wm = warp >> 1, wn = warp & 1;
    const int m0 = wm * 32, n0 = wn * 64;

    float acc[2][8][4];
    #pragma unroll
    for (int i = 0; i < 2; i++)
        #pragma unroll
        for (int j = 0; j < 8; j++)
            #pragma unroll
            for (int q = 0; q < 4; q++) acc[i][j][q] = 0.f;

    #pragma unroll
    for (int kk = 0; kk < 64; kk += 16) {
        uint32_t ah[2][4], al[2][4];
        #pragma unroll
        for (int mi = 0; mi < 2; mi++) {
            int off = (m0 + mi*16 + (lane & 15)) * 72 + kk + ((lane >> 4) << 3);
            ldsm4(ah[mi], cvta_s(&sQh[off]));
            ldsm4(al[mi], cvta_s(&sQl[off]));
        }
        #pragma unroll
        for (int nj = 0; nj < 4; nj++) {
            int nr = n0 + nj*16 + ((lane & 7) | (((lane >> 4) & 1) << 3));
            int off = nr * 72 + kk + (((lane >> 3) & 1) << 3);
            uint32_t bh4[4], bl4[4];
            ldsm4(bh4, cvta_s(&sKh[off]));
            ldsm4(bl4, cvta_s(&sKl[off]));
            #pragma unroll
            for (int mi = 0; mi < 2; mi++) {
                mma_bf(acc[mi][2*nj],   ah[mi], bh4[0], bh4[1]);
                mma_bf(acc[mi][2*nj],   ah[mi], bl4[0], bl4[1]);
                mma_bf(acc[mi][2*nj],   al[mi], bh4[0], bh4[1]);
                mma_bf(acc[mi][2*nj+1], ah[mi], bh4[2], bh4[3]);
                mma_bf(acc[mi][2*nj+1], ah[mi], bl4[2], bl4[3]);
                mma_bf(acc[mi][2*nj+1], al[mi], bh4[2], bh4[3]);
            }
        }
    }

    // mask values (cached in regs)
    float mk0[8], mk1[8];
    #pragma unroll
    for (int nj = 0; nj < 8; nj++) {
        int c = bcol + n0 + nj*8 + (lane & 3)*2;
        mk0[nj] = mask[b*S_ + c]     * (-1e9f);
        mk1[nj] = mask[b*S_ + c + 1] * (-1e9f);
    }

    float* outp = attn + (size_t)bh * S_ * S_;
    const int pidx = blockIdx.x * 2 + wn;
    #pragma unroll
    for (int mi = 0; mi < 2; mi++) {
        int r0 = brow + m0 + mi*16 + (lane >> 2);
        float mA = -3.4e38f, mB = -3.4e38f;
        #pragma unroll
        for (int nj = 0; nj < 8; nj++) {
            int c = bcol + n0 + nj*8 + (lane & 3)*2;
            float x0 = fmaf(acc[mi][nj][0], 0.125f, mk0[nj]);
            float x1 = fmaf(acc[mi][nj][1], 0.125f, mk1[nj]);
            float x2 = fmaf(acc[mi][nj][2], 0.125f, mk0[nj]);
            float x3 = fmaf(acc[mi][nj][3], 0.125f, mk1[nj]);
            acc[mi][nj][0] = x0; acc[mi][nj][1] = x1;
            acc[mi][nj][2] = x2; acc[mi][nj][3] = x3;
            *(float2*)&outp[(size_t)r0*S_ + c]     = make_float2(x0, x1);
            *(float2*)&outp[(size_t)(r0+8)*S_ + c] = make_float2(x2, x3);
            mA = fmaxf(mA, fmaxf(x0, x1));
            mB = fmaxf(mB, fmaxf(x2, x3));
        }
        #pragma unroll
        for (int o = 1; o < 4; o <<= 1) {
            mA = fmaxf(mA, __shfl_xor_sync(0xffffffffu, mA, o));
            mB = fmaxf(mB, __shfl_xor_sync(0xffffffffu, mB, o));
        }
        float sA = 0.f, sB = 0.f;
        #pragma unroll
        for (int nj = 0; nj < 8; nj++) {
            sA += __expf(acc[mi][nj][0] - mA) + __expf(acc[mi][nj][1] - mA);
            sB += __expf(acc[mi][nj][2] - mB) + __expf(acc[mi][nj][3] - mB);
        }
        #pragma unroll
        for (int o = 1; o < 4; o <<= 1) {
            sA += __shfl_xor_sync(0xffffffffu, sA, o);
            sB += __shfl_xor_sync(0xffffffffu, sB, o);
        }
        if ((lane & 3) == 0) {
            size_t pa = ((size_t)bh*1024 + r0)*16 + pidx;
            size_t pb = ((size_t)bh*1024 + r0 + 8)*16 + pidx;
            g_pmax[pa] = mA; g_psum[pa] = sA;
            g_pmax[pb] = mB; g_psum[pb] = sB;
        }
    }
}

// ---------------------------------------------------------------------------
// pv_fused = softmax + ctx: combines partials, normalizes raw scores in place
// (writing the final attn output), and computes ctx = P @ V -> split planes.
// ---------------------------------------------------------------------------
__global__ void __launch_bounds__(256)
pv_fused(float* __restrict__ attn)
{
    __shared__ __align__(16) __nv_bfloat16 sAh[128*40], sAl[128*40];
    __shared__ __align__(16) __nv_bfloat16 sBh[32*72],  sBl[32*72];
    __shared__ float sMx[128], sInv[128];

    const int bh = blockIdx.y, b = bh >> 4, h = bh & 15;
    float* A = attn + (size_t)bh * S_ * S_;
    const __nv_bfloat16* Vh = g_vh + (size_t)b * S_ * D_ + h * DH_;
    const __nv_bfloat16* Vl = g_vl + (size_t)b * S_ * D_ + h * DH_;

    const int tid = threadIdx.x, lane = tid & 31, warp = tid >> 5;
    const int brow = blockIdx.x * 128;

    if (tid < 128) {
        size_t pb = ((size_t)bh*1024 + brow + tid) * 16;
        float pm[16], ps[16];
        #pragma unroll
        for (int j = 0; j < 4; j++) {
            *(float4*)&pm[j*4] = *(const float4*)&g_pmax[pb + j*4];
            *(float4*)&ps[j*4] = *(const float4*)&g_psum[pb + j*4];
        }
        float mx = pm[0];
        #pragma unroll
        for (int j = 1; j < 16; j++) mx = fmaxf(mx, pm[j]);
        float s = 0.f;
        #pragma unroll
        for (int j = 0; j < 16; j++) s += ps[j] * __expf(pm[j] - mx);
        sMx[tid] = mx; sInv[tid] = 1.f / s;
    }
    __syncthreads();

    float4 stA[4]; uint4 stB[2];
    auto loadG = [&](int ks) {
        #pragma unroll
        for (int p = 0; p < 4; p++) {
            int row = (tid >> 3) + 32 * p, col = (tid & 7) * 4;
            stA[p] = *(const float4*)&A[(size_t)(brow + row) * S_ + ks + col];
        }
        #pragma unroll
        for (int p = 0; p < 2; p++) {
            int idx = tid + 256 * p;
            int r  = (idx & 255) >> 3;
            int ch = (idx & 7) * 8;
            const __nv_bfloat16* src = (idx < 256) ? Vh : Vl;
            stB[p] = *(const uint4*)&src[(size_t)(ks + r) * D_ + ch];
        }
    };
    auto storeS = [&](int ks) {
        #pragma unroll
        for (int p = 0; p < 4; p++) {
            int row = (tid >> 3) + 32 * p, col = (tid & 7) * 4;
            const float mx = sMx[row], inv = sInv[row];
            float v[4] = {stA[p].x, stA[p].y, stA[p].z, stA[p].w};
            #pragma unroll
            for (int i = 0; i < 4; i++) v[i] = __expf(v[i] - mx) * inv;
            *(float4*)&A[(size_t)(brow + row) * S_ + ks + col] =
                make_float4(v[0], v[1], v[2], v[3]);
            __nv_bfloat16 hh[4], ll[4];
            #pragma unroll
            for (int i = 0; i < 4; i++) split_bf(v[i], hh[i], ll[i]);
            *(__nv_bfloat162*)&sAh[row*40 + col]     = __halves2bfloat162(hh[0], hh[1]);
            *(__nv_bfloat162*)&sAh[row*40 + col + 2] = __halves2bfloat162(hh[2], hh[3]);
            *(__nv_bfloat162*)&sAl[row*40 + col]     = __halves2bfloat162(ll[0], ll[1]);
            *(__nv_bfloat162*)&sAl[row*40 + col + 2] = __halves2bfloat162(ll[2], ll[3]);
        }
        #pragma unroll
        for (int p = 0; p < 2; p++) {
            int idx = tid + 256 * p;
            int r  = (idx & 255) >> 3;
            int ch = (idx & 7) * 8;
            __nv_bfloat16* dst = (idx < 256) ? sBh : sBl;
            *(uint4*)&dst[r*72 + ch] = stB[p];
        }
    };

    const int wm = warp >> 1, wn = warp & 1;
    const int m0 = wm * 32, n0 = wn * 32;

    float acc[2][4][4];
    #pragma unroll
    for (int i = 0; i < 2; i++)
        #pragma unroll
        for (int j = 0; j < 4; j++)
            #pragma unroll
            for (int q = 0; q < 4; q++) acc[i][j][q] = 0.f;

    loadG(0);
    for (int ks = 0; ks < S_; ks += 32) {
        storeS(ks);
        __syncthreads();
        if (ks + 32 < S_) loadG(ks + 32);

        #pragma unroll
        for (int kk = 0; kk < 32; kk += 16) {
            uint32_t ah[2][4], al[2][4];
            #pragma unroll
            for (int mi = 0; mi < 2; mi++) {
                int off = (m0 + mi*16 + (lane & 15)) * 40 + kk + ((lane >> 4) << 3);
                ldsm4(ah[mi], cvta_s(&sAh[off]));
                ldsm4(al[mi], cvta_s(&sAl[off]));
            }
            #pragma unroll
            for (int nj = 0; nj < 2; nj++) {
                uint32_t bh4[4], bl4[4];
                int off = (kk + (lane & 15)) * 72 + n0 + nj*16 + ((lane >> 4) << 3);
                ldsm4t(bh4, cvta_s(&sBh[off]));
                ldsm4t(bl4, cvta_s(&sBl[off]));
                #pragma unroll
                for (int mi = 0; mi < 2; mi++) {
                    mma_bf(acc[mi][2*nj],   ah[mi], bh4[0], bh4[1]);
                    mma_bf(acc[mi][2*nj],   ah[mi], bl4[0], bl4[1]);
                    mma_bf(acc[mi][2*nj],   al[mi], bh4[0], bh4[1]);
                    mma_bf(acc[mi][2*nj+1], ah[mi], bh4[2], bh4[3]);
                    mma_bf(acc[mi][2*nj+1], ah[mi], bl4[2], bl4[3]);
                    mma_bf(acc[mi][2*nj+1], al[mi], bh4[2], bh4[3]);
                }
            }
        }
        __syncthreads();
    }

    __nv_bfloat16* Ch = g_ch + (size_t)b * S_ * D_ + h * DH_;
    __nv_bfloat16* Cl = g_cl + (size_t)b * S_ * D_ + h * DH_;
    #pragma unroll
    for (int mi = 0; mi < 2; mi++) {
        int r0 = brow + m0 + mi*16 + (lane >> 2);
        #pragma unroll
        for (int nj = 0; nj < 4; nj++) {
            int c = n0 + nj*8 + (lane & 3)*2;
            __nv_bfloat16 h0,l0,h1,l1,h2,l2,h3,l3;
            split_bf(acc[mi][nj][0], h0, l0); split_bf(acc[mi][nj][1], h1, l1);
            split_bf(acc[mi][nj][2], h2, l2); split_bf(acc[mi][nj][3], h3, l3);
            *(__nv_bfloat162*)&Ch[(size_t)r0*D_ + c]     = __halves2bfloat162(h0, h1);
            *(__nv_bfloat162*)&Cl[(size_t)r0*D_ + c]     = __halves2bfloat162(l0, l1);
            *(__nv_bfloat162*)&Ch[(size_t)(r0+8)*D_ + c] = __halves2bfloat162(h2, h3);
            *(__nv_bfloat162*)&Cl[(size_t)(r0+8)*D_ + c] = __halves2bfloat162(l2, l3);
        }
    }
}

// ---------------------------------------------------------------------------
extern "C" void kernel_launch(void* const* d_in, const int* in_sizes, int n_in,
                              void* d_out, int out_size)
{
    const float* q    = (const float*)d_in[0];
    const float* k    = (const float*)d_in[1];
    const float* v    = (const float*)d_in[2];
    const float* mask = (const float*)d_in[3];
    const float* wq = (const float*)d_in[4];  const float* bq = (const float*)d_in[5];
    const float* wk = (const float*)d_in[6];  const float* bk = (const float*)d_in[7];
    const float* wv = (const float*)d_in[8];  const float* bv = (const float*)d_in[9];
    const float* wo = (const float*)d_in[10]; const float* bo = (const float*)d_in[11];
    const float* g1 = (const float*)d_in[12]; const float* be1 = (const float*)d_in[13];
    const float* mm1 = (const float*)d_in[14]; const float* mv1 = (const float*)d_in[15];
    const float* g2 = (const float*)d_in[16]; const float* be2 = (const float*)d_in[17];
    const float* mm2 = (const float*)d_in[18]; const float* mv2 = (const float*)d_in[19];
    const float* g3 = (const float*)d_in[20]; const float* be3 = (const float*)d_in[21];
    const float* mm3 = (const float*)d_in[22]; const float* mv3 = (const float*)d_in[23];

    float* out  = (float*)d_out;
    float* attn = out + (size_t)M_ * D_;

    void* p;
    __nv_bfloat16 *qh,*ql,*kh,*kl,*vh,*vl,*ch,*cl;
    __nv_bfloat16 *rqh,*rql,*rkh,*rkl,*rvh,*rvl,*wph,*wpl;
    cudaGetSymbolAddress(&p, g_qh); qh = (__nv_bfloat16*)p;
    cudaGetSymbolAddress(&p, g_ql); ql = (__nv_bfloat16*)p;
    cudaGetSymbolAddress(&p, g_kh); kh = (__nv_bfloat16*)p;
    cudaGetSymbolAddress(&p, g_kl); kl = (__nv_bfloat16*)p;
    cudaGetSymbolAddress(&p, g_vh); vh = (__nv_bfloat16*)p;
    cudaGetSymbolAddress(&p, g_vl); vl = (__nv_bfloat16*)p;
    cudaGetSymbolAddress(&p, g_ch); ch = (__nv_bfloat16*)p;
    cudaGetSymbolAddress(&p, g_cl); cl = (__nv_bfloat16*)p;
    cudaGetSymbolAddress(&p, g_rqh); rqh = (__nv_bfloat16*)p;
    cudaGetSymbolAddress(&p, g_rql); rql = (__nv_bfloat16*)p;
    cudaGetSymbolAddress(&p, g_rkh); rkh = (__nv_bfloat16*)p;
    cudaGetSymbolAddress(&p, g_rkl); rkl = (__nv_bfloat16*)p;
    cudaGetSymbolAddress(&p, g_rvh); rvh = (__nv_bfloat16*)p;
    cudaGetSymbolAddress(&p, g_rvl); rvl = (__nv_bfloat16*)p;
    cudaGetSymbolAddress(&p, g_wh); wph = (__nv_bfloat16*)p;
    cudaGetSymbolAddress(&p, g_wl); wpl = (__nv_bfloat16*)p;

    const size_t WSZ = (size_t)D_ * D_;
    const int n4a = (int)((size_t)M_ * D_ / 4);
    const int n4w = (int)(WSZ / 4);

    split_kernel<<<n4a/256, 256>>>(q, rqh, rql, n4a);
    split_kernel<<<n4a/256, 256>>>(k, rkh, rkl, n4a);
    split_kernel<<<n4a/256, 256>>>(v, rvh, rvl, n4a);
    split_kernel<<<n4w/256, 256>>>(wq, wph + 0*WSZ, wpl + 0*WSZ, n4w);
    split_kernel<<<n4w/256, 256>>>(wk, wph + 1*WSZ, wpl + 1*WSZ, n4w);
    split_kernel<<<n4w/256, 256>>>(wv, wph + 2*WSZ, wpl + 2*WSZ, n4w);
    split_kernel<<<n4w/256, 256>>>(wo, wph + 3*WSZ, wpl + 3*WSZ, n4w);

    cudaFuncSetAttribute(gemm_tc3<true,true>,
        cudaFuncAttributeMaxDynamicSharedMemorySize, 3*STG_*2);
    cudaFuncSetAttribute(gemm_tc3<false,false>,
        cudaFuncAttributeMaxDynamicSharedMemorySize, 3*STG_*2);
    cudaFuncSetAttribute(scores_tc, cudaFuncAttributeMaxDynamicSharedMemorySize, 73728);

    dim3 gp(D_/128, M_/128);   // (8, 64)
    gemm_tc3<true,true><<<gp,128,3*STG_*2>>>(rqh, rql, wph + 0*WSZ, wpl + 0*WSZ,
        bq, g1, be1, mm1, mv1, nullptr, qh, ql);
    gemm_tc3<true,true><<<gp,128,3*STG_*2>>>(rkh, rkl, wph + 1*WSZ, wpl + 1*WSZ,
        bk, g2, be2, mm2, mv2, nullptr, kh, kl);
    gemm_tc3<true,true><<<gp,128,3*STG_*2>>>(rvh, rvl, wph + 2*WSZ, wpl + 2*WSZ,
        bv, g3, be3, mm3, mv3, nullptr, vh, vl);

    scores_tc<<<dim3(8,8,128),256,73728>>>(mask, attn);

    pv_fused<<<dim3(8,128),256>>>(attn);

    gemm_tc3<false,false><<<gp,128,3*STG_*2>>>(ch, cl, wph + 3*WSZ, wpl + 3*WSZ,
        bo, nullptr, nullptr, nullptr, nullptr, out, nullptr, nullptr);
}

// round 14
// speedup vs baseline: 1.1027x; 1.0054x over previous
#include <cuda_runtime.h>
#include <cuda_bf16.h>
#include <stdint.h>
#include <math.h>

#define B_  8
#define S_  1024
#define D_  1024
#define H_  16
#define DH_ 64
#define M_  (B_*S_)     // 8192

// Projected split planes
__device__ __nv_bfloat16 g_qh[(size_t)M_*D_], g_ql[(size_t)M_*D_];
__device__ __nv_bfloat16 g_kh[(size_t)M_*D_], g_kl[(size_t)M_*D_];
__device__ __nv_bfloat16 g_vh[(size_t)M_*D_], g_vl[(size_t)M_*D_];
__device__ __nv_bfloat16 g_ch[(size_t)M_*D_], g_cl[(size_t)M_*D_];
// Raw-input split planes
__device__ __nv_bfloat16 g_rqh[(size_t)M_*D_], g_rql[(size_t)M_*D_];
__device__ __nv_bfloat16 g_rkh[(size_t)M_*D_], g_rkl[(size_t)M_*D_];
__device__ __nv_bfloat16 g_rvh[(size_t)M_*D_], g_rvl[(size_t)M_*D_];
// Weight split planes (wq, wk, wv, wo)
__device__ __nv_bfloat16 g_wh[4][(size_t)D_*D_], g_wl[4][(size_t)D_*D_];
// Softmax partials: per (bh, row) x 16 column-ranges
__device__ float g_pmax[(size_t)128*1024*16];
__device__ float g_psum[(size_t)128*1024*16];

// ---------------------------------------------------------------------------
__device__ __forceinline__ uint32_t cvta_s(const void* p) {
    return (uint32_t)__cvta_generic_to_shared(p);
}
__device__ __forceinline__ void cpa16(uint32_t dst, const void* src) {
    asm volatile("cp.async.cg.shared.global [%0], [%1], 16;" :: "r"(dst), "l"(src));
}
__device__ __forceinline__ void ldsm4(uint32_t r[4], uint32_t a) {
    asm volatile("ldmatrix.sync.aligned.m8n8.x4.shared.b16 {%0,%1,%2,%3}, [%4];"
        : "=r"(r[0]), "=r"(r[1]), "=r"(r[2]), "=r"(r[3]) : "r"(a));
}
__device__ __forceinline__ void ldsm4t(uint32_t r[4], uint32_t a) {
    asm volatile("ldmatrix.sync.aligned.m8n8.x4.trans.shared.b16 {%0,%1,%2,%3}, [%4];"
        : "=r"(r[0]), "=r"(r[1]), "=r"(r[2]), "=r"(r[3]) : "r"(a));
}
__device__ __forceinline__ void mma_bf(float c[4], const uint32_t a[4],
                                       uint32_t b0, uint32_t b1) {
    asm volatile("mma.sync.aligned.m16n8k16.row.col.f32.bf16.bf16.f32 "
        "{%0,%1,%2,%3},{%4,%5,%6,%7},{%8,%9},{%0,%1,%2,%3};"
        : "+f"(c[0]), "+f"(c[1]), "+f"(c[2]), "+f"(c[3])
        : "r"(a[0]), "r"(a[1]), "r"(a[2]), "r"(a[3]), "r"(b0), "r"(b1));
}
__device__ __forceinline__ void split_bf(float x, __nv_bfloat16& h, __nv_bfloat16& l) {
    h = __float2bfloat16(x);
    l = __float2bfloat16(x - __bfloat162float(h));
}
// pack two floats into bf16 hi-pair and lo-pair regs (round-7 proven C->A path)
__device__ __forceinline__ void split2(float x, float y, uint32_t& h, uint32_t& l) {
    __nv_bfloat16 hx, lx, hy, ly;
    split_bf(x, hx, lx); split_bf(y, hy, ly);
    __nv_bfloat162 hh = __halves2bfloat162(hx, hy);
    __nv_bfloat162 ll = __halves2bfloat162(lx, ly);
    h = *(uint32_t*)&hh; l = *(uint32_t*)&ll;
}

// ---------------------------------------------------------------------------
// Pre-split: fp32 -> bf16 hi/lo planes
// ---------------------------------------------------------------------------
__global__ void __launch_bounds__(256)
split_kernel(const float* __restrict__ in, __nv_bfloat16* __restrict__ hi,
             __nv_bfloat16* __restrict__ lo, int n4)
{
    int i = blockIdx.x * blockDim.x + threadIdx.x;
    if (i >= n4) return;
    float4 v = ((const float4*)in)[i];
    __nv_bfloat16 h0,l0,h1,l1,h2,l2,h3,l3;
    split_bf(v.x,h0,l0); split_bf(v.y,h1,l1);
    split_bf(v.z,h2,l2); split_bf(v.w,h3,l3);
    ((__nv_bfloat162*)hi)[2*i]   = __halves2bfloat162(h0,h1);
    ((__nv_bfloat162*)hi)[2*i+1] = __halves2bfloat162(h2,h3);
    ((__nv_bfloat162*)lo)[2*i]   = __halves2bfloat162(l0,l1);
    ((__nv_bfloat162*)lo)[2*i+1] = __halves2bfloat162(l2,l3);
}

// ---------------------------------------------------------------------------
// Big GEMM v4 (round-12 WIN): 128 threads, 4 warps, warp tile 64x64,
// THREE-stage cp.async.
// ---------------------------------------------------------------------------
#define STG_ 18944
template<bool DO_BN, bool SPLIT_OUT>
__global__ void __launch_bounds__(128, 2)
gemm_tc3(const __nv_bfloat16* __restrict__ Ah, const __nv_bfloat16* __restrict__ Al,
         const __nv_bfloat16* __restrict__ Wh, const __nv_bfloat16* __restrict__ Wl,
         const float* __restrict__ bias,
         const float* __restrict__ gam, const float* __restrict__ bet,
         const float* __restrict__ mmean, const float* __restrict__ mvar,
         float* __restrict__ Cf,
         __nv_bfloat16* __restrict__ Chg, __nv_bfloat16* __restrict__ Clg)
{
    extern __shared__ __align__(16) __nv_bfloat16 sm2[];
    const int tid = threadIdx.x, lane = tid & 31, warp = tid >> 5;
    const int brow = blockIdx.y * 128, bcol = blockIdx.x * 128;

    auto issue = [&](int slab, int buf) {
        __nv_bfloat16* st = sm2 + buf * STG_;
        const int ks = slab * 32;
        #pragma unroll
        for (int p = 0; p < 4; p++) {
            int c = tid + 128 * p;
            int r = c >> 2, q = (c & 3) * 8;
            const size_t ga = (size_t)(brow + r) * D_ + ks + q;
            cpa16(cvta_s(&st[r*40 + q]),        &Ah[ga]);
            cpa16(cvta_s(&st[5120 + r*40 + q]), &Al[ga]);
        }
        #pragma unroll
        for (int p = 0; p < 4; p++) {
            int c = tid + 128 * p;
            int r = c >> 4, q = (c & 15) * 8;
            const size_t gb = (size_t)(ks + r) * D_ + bcol + q;
            cpa16(cvta_s(&st[10240 + r*136 + q]), &Wh[gb]);
            cpa16(cvta_s(&st[14592 + r*136 + q]), &Wl[gb]);
        }
        asm volatile("cp.async.commit_group;");
    };

    const int wm = warp >> 1, wn = warp & 1;
    const int m0 = wm * 64, n0 = wn * 64;

    float acc[4][8][4];
    #pragma unroll
    for (int i = 0; i < 4; i++)
        #pragma unroll
        for (int j = 0; j < 8; j++)
            #pragma unroll
            for (int q = 0; q < 4; q++) acc[i][j][q] = 0.f;

    issue(0, 0);
    issue(1, 1);
    for (int s = 0; s < 32; s++) {
        if (s + 2 < 32) {
            issue(s + 2, (s + 2) % 3);
            asm volatile("cp.async.wait_group 2;");
        } else if (s + 1 < 32) {
            asm volatile("cp.async.wait_group 1;");
        } else {
            asm volatile("cp.async.wait_group 0;");
        }
        __syncthreads();

        const __nv_bfloat16* sAh = sm2 + (s % 3) * STG_;
        const __nv_bfloat16* sAl = sAh + 5120;
        const __nv_bfloat16* sBh = sAh + 10240;
        const __nv_bfloat16* sBl = sAh + 14592;

        #pragma unroll
        for (int kk = 0; kk < 32; kk += 16) {
            uint32_t ah[4][4], al[4][4];
            #pragma unroll
            for (int mi = 0; mi < 4; mi++) {
                int off = (m0 + mi*16 + (lane & 15)) * 40 + kk + ((lane >> 4) << 3);
                ldsm4(ah[mi], cvta_s(&sAh[off]));
                ldsm4(al[mi], cvta_s(&sAl[off]));
            }
            #pragma unroll
            for (int nj = 0; nj < 4; nj++) {
                uint32_t bh[4], bl[4];
                int off = (kk + (lane & 15)) * 136 + n0 + nj*16 + ((lane >> 4) << 3);
                ldsm4t(bh, cvta_s(&sBh[off]));
                ldsm4t(bl, cvta_s(&sBl[off]));
                #pragma unroll
                for (int mi = 0; mi < 4; mi++) {
                    mma_bf(acc[mi][2*nj],   ah[mi], bh[0], bh[1]);
                    mma_bf(acc[mi][2*nj],   ah[mi], bl[0], bl[1]);
                    mma_bf(acc[mi][2*nj],   al[mi], bh[0], bh[1]);
                    mma_bf(acc[mi][2*nj+1], ah[mi], bh[2], bh[3]);
                    mma_bf(acc[mi][2*nj+1], ah[mi], bl[2], bl[3]);
                    mma_bf(acc[mi][2*nj+1], al[mi], bh[2], bh[3]);
                }
            }
        }
        __syncthreads();
    }

    #pragma unroll
    for (int mi = 0; mi < 4; mi++) {
        int r0 = brow + m0 + mi*16 + (lane >> 2);
        #pragma unroll
        for (int nj = 0; nj < 8; nj++) {
            int c = bcol + n0 + nj*8 + (lane & 3)*2;
            float b0v = bias[c], b1v = bias[c+1];
            float sc0 = 1.f, sh0 = 0.f, sc1 = 1.f, sh1 = 0.f;
            if (DO_BN) {
                sc0 = gam[c]   * rsqrtf(mvar[c]   + 1e-3f); sh0 = bet[c]   - mmean[c]   * sc0;
                sc1 = gam[c+1] * rsqrtf(mvar[c+1] + 1e-3f); sh1 = bet[c+1] - mmean[c+1] * sc1;
            }
            float y00 = fmaxf(acc[mi][nj][0] + b0v, 0.f);
            float y01 = fmaxf(acc[mi][nj][1] + b1v, 0.f);
            float y10 = fmaxf(acc[mi][nj][2] + b0v, 0.f);
            float y11 = fmaxf(acc[mi][nj][3] + b1v, 0.f);
            if (DO_BN) {
                y00 = y00*sc0 + sh0; y01 = y01*sc1 + sh1;
                y10 = y10*sc0 + sh0; y11 = y11*sc1 + sh1;
            }
            if constexpr (SPLIT_OUT) {
                __nv_bfloat16 h0,l0,h1,l1,h2,l2,h3,l3;
                split_bf(y00,h0,l0); split_bf(y01,h1,l1);
                split_bf(y10,h2,l2); split_bf(y11,h3,l3);
                *(__nv_bfloat162*)&Chg[(size_t)r0*D_ + c]     = __halves2bfloat162(h0,h1);
                *(__nv_bfloat162*)&Clg[(size_t)r0*D_ + c]     = __halves2bfloat162(l0,l1);
                *(__nv_bfloat162*)&Chg[(size_t)(r0+8)*D_ + c] = __halves2bfloat162(h2,h3);
                *(__nv_bfloat162*)&Clg[(size_t)(r0+8)*D_ + c] = __halves2bfloat162(l2,l3);
            } else {
                *(float2*)&Cf[(size_t)r0*D_ + c]     = make_float2(y00, y01);
                *(float2*)&Cf[(size_t)(r0+8)*D_ + c] = make_float2(y10, y11);
            }
        }
    }
}

// ---------------------------------------------------------------------------
// scores (round-9 proven): 256 threads, 8 warps, warp tile 32x64.
// Writes raw (scaled+masked) scores to attn + per-range softmax partials.
// ---------------------------------------------------------------------------
__global__ void __launch_bounds__(256)
scores_tc(const float* __restrict__ mask, float* __restrict__ attn)
{
    extern __shared__ __align__(16) __nv_bfloat16 sm[];
    __nv_bfloat16* sQh = sm;
    __nv_bfloat16* sQl = sm + 9216;
    __nv_bfloat16* sKh = sm + 18432;
    __nv_bfloat16* sKl = sm + 27648;

    const int bh = blockIdx.z, b = bh >> 4, h = bh & 15;
    const size_t base = (size_t)b * S_ * D_ + h * DH_;
    const int tid = threadIdx.x, lane = tid & 31, warp = tid >> 5;
    const int brow = blockIdx.y * 128, bcol = blockIdx.x * 128;

    #pragma unroll
    for (int p = 0; p < 4; p++) {
        int idx = tid + 256 * p;
        int row = idx >> 3;
        int ch  = (idx & 7) * 8;
        *(uint4*)&sQh[row*72 + ch] = *(const uint4*)&g_qh[base + (size_t)(brow + row)*D_ + ch];
        *(uint4*)&sQl[row*72 + ch] = *(const uint4*)&g_ql[base + (size_t)(brow + row)*D_ + ch];
        *(uint4*)&sKh[row*72 + ch] = *(const uint4*)&g_kh[base + (size_t)(bcol + row)*D_ + ch];
        *(uint4*)&sKl[row*72 + ch] = *(const uint4*)&g_kl[base + (size_t)(bcol + row)*D_ + ch];
    }
    __syncthreads();

    const int wm = warp >> 1, wn = warp & 1;
    const int m0 = wm * 32, n0 = wn * 64;

    float acc[2][8][4];
    #pragma unroll
    for (int i = 0; i < 2; i++)
        #pragma unroll
        for (int j = 0; j < 8; j++)
            #pragma unroll
            for (int q = 0; q < 4; q++) acc[i][j][q] = 0.f;

    #pragma unroll
    for (int kk = 0; kk < 64; kk += 16) {
        uint32_t ah[2][4], al[2][4];
        #pragma unroll
        for (int mi = 0; mi < 2; mi++) {
            int off = (m0 + mi*16 + (lane & 15)) * 72 + kk + ((lane >> 4) << 3);
            ldsm4(ah[mi], cvta_s(&sQh[off]));
            ldsm4(al[mi], cvta_s(&sQl[off]));
        }
        #pragma unroll
        for (int nj = 0; nj < 4; nj++) {
            int nr = n0 + nj*16 + ((lane & 7) | (((lane >> 4) & 1) << 3));
            int off = nr * 72 + kk + (((lane >> 3) & 1) << 3);
            uint32_t bh4[4], bl4[4];
            ldsm4(bh4, cvta_s(&sKh[off]));
            ldsm4(bl4, cvta_s(&sKl[off]));
            #pragma unroll
            for (int mi = 0; mi < 2; mi++) {
                mma_bf(acc[mi][2*nj],   ah[mi], bh4[0], bh4[1]);
                mma_bf(acc[mi][2*nj],   ah[mi], bl4[0], bl4[1]);
                mma_bf(acc[mi][2*nj],   al[mi], bh4[0], bh4[1]);
                mma_bf(acc[mi][2*nj+1], ah[mi], bh4[2], bh4[3]);
                mma_bf(acc[mi][2*nj+1], ah[mi], bl4[2], bl4[3]);
                mma_bf(acc[mi][2*nj+1], al[mi], bh4[2], bh4[3]);
            }
        }
    }

    float mk0[8], mk1[8];
    #pragma unroll
    for (int nj = 0; nj < 8; nj++) {
        int c = bcol + n0 + nj*8 + (lane & 3)*2;
        mk0[nj] = mask[b*S_ + c]     * (-1e9f);
        mk1[nj] = mask[b*S_ + c + 1] * (-1e9f);
    }

    float* outp = attn + (size_t)bh * S_ * S_;
    const int pidx = blockIdx.x * 2 + wn;
    #pragma unroll
    for (int mi = 0; mi < 2; mi++) {
        int r0 = brow + m0 + mi*16 + (lane >> 2);
        float mA = -3.4e38f, mB = -3.4e38f;
        #pragma unroll
        for (int nj = 0; nj < 8; nj++) {
            int c = bcol + n0 + nj*8 + (lane & 3)*2;
            float x0 = fmaf(acc[mi][nj][0], 0.125f, mk0[nj]);
            float x1 = fmaf(acc[mi][nj][1], 0.125f, mk1[nj]);
            float x2 = fmaf(acc[mi][nj][2], 0.125f, mk0[nj]);
            float x3 = fmaf(acc[mi][nj][3], 0.125f, mk1[nj]);
            acc[mi][nj][0] = x0; acc[mi][nj][1] = x1;
            acc[mi][nj][2] = x2; acc[mi][nj][3] = x3;
            *(float2*)&outp[(size_t)r0*S_ + c]     = make_float2(x0, x1);
            *(float2*)&outp[(size_t)(r0+8)*S_ + c] = make_float2(x2, x3);
            mA = fmaxf(mA, fmaxf(x0, x1));
            mB = fmaxf(mB, fmaxf(x2, x3));
        }
        #pragma unroll
        for (int o = 1; o < 4; o <<= 1) {
            mA = fmaxf(mA, __shfl_xor_sync(0xffffffffu, mA, o));
            mB = fmaxf(mB, __shfl_xor_sync(0xffffffffu, mB, o));
        }
        float sA = 0.f, sB = 0.f;
        #pragma unroll
        for (int nj = 0; nj < 8; nj++) {
            sA += __expf(acc[mi][nj][0] - mA) + __expf(acc[mi][nj][1] - mA);
            sB += __expf(acc[mi][nj][2] - mB) + __expf(acc[mi][nj][3] - mB);
        }
        #pragma unroll
        for (int o = 1; o < 4; o <<= 1) {
            sA += __shfl_xor_sync(0xffffffffu, sA, o);
            sB += __shfl_xor_sync(0xffffffffu, sB, o);
        }
        if ((lane & 3) == 0) {
            size_t pa = ((size_t)bh*1024 + r0)*16 + pidx;
            size_t pb = ((size_t)bh*1024 + r0 + 8)*16 + pidx;
            g_pmax[pa] = mA; g_psum[pa] = sA;
            g_pmax[pb] = mB; g_psum[pb] = sB;
        }
    }
}

// ---------------------------------------------------------------------------
// pv_v2: softmax + ctx with REGISTER-DIRECT P operand.
// CTA = 128 rows x one (b,h); 256 threads, 8 warps; warp owns 16 rows x 64 Vcols.
// Per k16 step: LDG raw scores as A-frag elements -> exp/normalize in regs ->
// STG normalized attn -> split2 -> mma with V (cp.async double-buffered).
// No smem for P, no ldsm for A.
// ---------------------------------------------------------------------------
__global__ void __launch_bounds__(256, 2)
pv_fused(float* __restrict__ attn)
{
    __shared__ __align__(16) __nv_bfloat16 sV[2][2][64*72];  // [buf][plane][64 rows x72]
    __shared__ float sMx[128], sInv[128];

    const int bh = blockIdx.y, b = bh >> 4, h = bh & 15;
    float* A = attn + (size_t)bh * S_ * S_;
    const __nv_bfloat16* Vh = g_vh + (size_t)b * S_ * D_ + h * DH_;
    const __nv_bfloat16* Vl = g_vl + (size_t)b * S_ * D_ + h * DH_;

    const int tid = threadIdx.x, lane = tid & 31, warp = tid >> 5;
    const int brow = blockIdx.x * 128;
    const int ra = lane >> 2, c2 = (lane & 3) * 2;

    // prologue: combine 16 softmax partials per row
    if (tid < 128) {
        size_t pb = ((size_t)bh*1024 + brow + tid) * 16;
        float pm[16], ps[16];
        #pragma unroll
        for (int j = 0; j < 4; j++) {
            *(float4*)&pm[j*4] = *(const float4*)&g_pmax[pb + j*4];
            *(float4*)&ps[j*4] = *(const float4*)&g_psum[pb + j*4];
        }
        float mx = pm[0];
        #pragma unroll
        for (int j = 1; j < 16; j++) mx = fmaxf(mx, pm[j]);
        float s = 0.f;
        #pragma unroll
        for (int j = 0; j < 16; j++) s += ps[j] * __expf(pm[j] - mx);
        sMx[tid] = mx; sInv[tid] = 1.f / s;
    }

    auto issueV = [&](int kt, int buf) {   // kt = slab of 64 key-rows
        #pragma unroll
        for (int p = 0; p < 4; p++) {
            int idx = tid + 256 * p;        // 0..1023
            int pl = idx >> 9;              // plane
            int r  = (idx >> 3) & 63;       // row
            int ch = idx & 7;
            const __nv_bfloat16* src = pl ? Vl : Vh;
            cpa16(cvta_s(&sV[buf][pl][r*72 + ch*8]),
                  &src[(size_t)(kt*64 + r) * D_ + ch*8]);
        }
        asm volatile("cp.async.commit_group;");
    };

    issueV(0, 0);
    __syncthreads();    // sMx/sInv ready
    const float mxA = sMx[warp*16 + ra],     invA = sInv[warp*16 + ra];
    const float mxB = sMx[warp*16 + ra + 8], invB = sInv[warp*16 + ra + 8];

    float* rowA = A + (size_t)(brow + warp*16 + ra) * S_;
    float* rowB = rowA + 8 * S_;

    float cacc[8][4];
    #pragma unroll
    for (int g = 0; g < 8; g++)
        #pragma unroll
        for (int q = 0; q < 4; q++) cacc[g][q] = 0.f;

    for (int kt = 0; kt < 16; kt++) {
        if (kt + 1 < 16) {
            issueV(kt + 1, (kt + 1) & 1);
            asm volatile("cp.async.wait_group 1;");
        } else {
            asm volatile("cp.async.wait_group 0;");
        }
        __syncthreads();
        const __nv_bfloat16* Th = sV[kt & 1][0];
        const __nv_bfloat16* Tl = sV[kt & 1][1];

        #pragma unroll
        for (int j = 0; j < 4; j++) {
            const int kk = kt*64 + j*16;
            // load raw score fragment elements
            float2 v00 = *(float2*)&rowA[kk + c2];
            float2 v10 = *(float2*)&rowB[kk + c2];
            float2 v01 = *(float2*)&rowA[kk + c2 + 8];
            float2 v11 = *(float2*)&rowB[kk + c2 + 8];
            // exp + normalize
            v00.x = __expf(v00.x - mxA) * invA; v00.y = __expf(v00.y - mxA) * invA;
            v01.x = __expf(v01.x - mxA) * invA; v01.y = __expf(v01.y - mxA) * invA;
            v10.x = __expf(v10.x - mxB) * invB; v10.y = __expf(v10.y - mxB) * invB;
            v11.x = __expf(v11.x - mxB) * invB; v11.y = __expf(v11.y - mxB) * invB;
            // write normalized attn (final output)
            *(float2*)&rowA[kk + c2]     = v00;
            *(float2*)&rowB[kk + c2]     = v10;
            *(float2*)&rowA[kk + c2 + 8] = v01;
            *(float2*)&rowB[kk + c2 + 8] = v11;
            // build A-frags (round-7 proven ordering)
            uint32_t ah[4], al[4];
            split2(v00.x, v00.y, ah[0], al[0]);
            split2(v10.x, v10.y, ah[1], al[1]);
            split2(v01.x, v01.y, ah[2], al[2]);
            split2(v11.x, v11.y, ah[3], al[3]);
            // B-frags from V smem, MMA over 4 n16 groups
            #pragma unroll
            for (int nj = 0; nj < 4; nj++) {
                int off = (j*16 + (lane & 15)) * 72 + nj*16 + ((lane >> 4) << 3);
                uint32_t bh4[4], bl4[4];
                ldsm4t(bh4, cvta_s(&Th[off]));
                ldsm4t(bl4, cvta_s(&Tl[off]));
                mma_bf(cacc[2*nj],   ah, bh4[0], bh4[1]);
                mma_bf(cacc[2*nj],   ah, bl4[0], bl4[1]);
                mma_bf(cacc[2*nj],   al, bh4[0], bh4[1]);
                mma_bf(cacc[2*nj+1], ah, bh4[2], bh4[3]);
                mma_bf(cacc[2*nj+1], ah, bl4[2], bl4[3]);
                mma_bf(cacc[2*nj+1], al, bh4[2], bh4[3]);
            }
        }
        __syncthreads();
    }

    // epilogue: warp owns rows warp*16 + {ra, ra+8} fully (no reduction)
    __nv_bfloat16* Ch = g_ch + (size_t)b * S_ * D_ + h * DH_;
    __nv_bfloat16* Cl = g_cl + (size_t)b * S_ * D_ + h * DH_;
    const int r0 = brow + warp*16 + ra;
    #pragma unroll
    for (int g = 0; g < 8; g++) {
        int c = (g >> 1)*16 + (g & 1)*8 + c2;
        __nv_bfloat16 h0,l0,h1,l1,h2,l2,h3,l3;
        split_bf(cacc[g][0], h0, l0); split_bf(cacc[g][1], h1, l1);
        split_bf(cacc[g][2], h2, l2); split_bf(cacc[g][3], h3, l3);
        *(__nv_bfloat162*)&Ch[(size_t)r0*D_ + c]     = __halves2bfloat162(h0, h1);
        *(__nv_bfloat162*)&Cl[(size_t)r0*D_ + c]     = __halves2bfloat162(l0, l1);
        *(__nv_bfloat162*)&Ch[(size_t)(r0+8)*D_ + c] = __halves2bfloat162(h2, h3);
        *(__nv_bfloat162*)&Cl[(size_t)(r0+8)*D_ + c] = __halves2bfloat162(l2, l3);
    }
}

// ---------------------------------------------------------------------------
extern "C" void kernel_launch(void* const* d_in, const int* in_sizes, int n_in,
                              void* d_out, int out_size)
{
    const float* q    = (const float*)d_in[0];
    const float* k    = (const float*)d_in[1];
    const float* v    = (const float*)d_in[2];
    const float* mask = (const float*)d_in[3];
    const float* wq = (const float*)d_in[4];  const float* bq = (const float*)d_in[5];
    const float* wk = (const float*)d_in[6];  const float* bk = (const float*)d_in[7];
    const float* wv = (const float*)d_in[8];  const float* bv = (const float*)d_in[9];
    const float* wo = (const float*)d_in[10]; const float* bo = (const float*)d_in[11];
    const float* g1 = (const float*)d_in[12]; const float* be1 = (const float*)d_in[13];
    const float* mm1 = (const float*)d_in[14]; const float* mv1 = (const float*)d_in[15];
    const float* g2 = (const float*)d_in[16]; const float* be2 = (const float*)d_in[17];
    const float* mm2 = (const float*)d_in[18]; const float* mv2 = (const float*)d_in[19];
    const float* g3 = (const float*)d_in[20]; const float* be3 = (const float*)d_in[21];
    const float* mm3 = (const float*)d_in[22]; const float* mv3 = (const float*)d_in[23];

    float* out  = (float*)d_out;
    float* attn = out + (size_t)M_ * D_;

    void* p;
    __nv_bfloat16 *qh,*ql,*kh,*kl,*vh,*vl,*ch,*cl;
    __nv_bfloat16 *rqh,*rql,*rkh,*rkl,*rvh,*rvl,*wph,*wpl;
    cudaGetSymbolAddress(&p, g_qh); qh = (__nv_bfloat16*)p;
    cudaGetSymbolAddress(&p, g_ql); ql = (__nv_bfloat16*)p;
    cudaGetSymbolAddress(&p, g_kh); kh = (__nv_bfloat16*)p;
    cudaGetSymbolAddress(&p, g_kl); kl = (__nv_bfloat16*)p;
    cudaGetSymbolAddress(&p, g_vh); vh = (__nv_bfloat16*)p;
    cudaGetSymbolAddress(&p, g_vl); vl = (__nv_bfloat16*)p;
    cudaGetSymbolAddress(&p, g_ch); ch = (__nv_bfloat16*)p;
    cudaGetSymbolAddress(&p, g_cl); cl = (__nv_bfloat16*)p;
    cudaGetSymbolAddress(&p, g_rqh); rqh = (__nv_bfloat16*)p;
    cudaGetSymbolAddress(&p, g_rql); rql = (__nv_bfloat16*)p;
    cudaGetSymbolAddress(&p, g_rkh); rkh = (__nv_bfloat16*)p;
    cudaGetSymbolAddress(&p, g_rkl); rkl = (__nv_bfloat16*)p;
    cudaGetSymbolAddress(&p, g_rvh); rvh = (__nv_bfloat16*)p;
    cudaGetSymbolAddress(&p, g_rvl); rvl = (__nv_bfloat16*)p;
    cudaGetSymbolAddress(&p, g_wh); wph = (__nv_bfloat16*)p;
    cudaGetSymbolAddress(&p, g_wl); wpl = (__nv_bfloat16*)p;

    const size_t WSZ = (size_t)D_ * D_;
    const int n4a = (int)((size_t)M_ * D_ / 4);
    const int n4w = (int)(WSZ / 4);

    split_kernel<<<n4a/256, 256>>>(q, rqh, rql, n4a);
    split_kernel<<<n4a/256, 256>>>(k, rkh, rkl, n4a);
    split_kernel<<<n4a/256, 256>>>(v, rvh, rvl, n4a);
    split_kernel<<<n4w/256, 256>>>(wq, wph + 0*WSZ, wpl + 0*WSZ, n4w);
    split_kernel<<<n4w/256, 256>>>(wk, wph + 1*WSZ, wpl + 1*WSZ, n4w);
    split_kernel<<<n4w/256, 256>>>(wv, wph + 2*WSZ, wpl + 2*WSZ, n4w);
    split_kernel<<<n4w/256, 256>>>(wo, wph + 3*WSZ, wpl + 3*WSZ, n4w);

    cudaFuncSetAttribute(gemm_tc3<true,true>,
        cudaFuncAttributeMaxDynamicSharedMemorySize, 3*STG_*2);
    cudaFuncSetAttribute(gemm_tc3<false,false>,
        cudaFuncAttributeMaxDynamicSharedMemorySize, 3*STG_*2);
    cudaFuncSetAttribute(scores_tc, cudaFuncAttributeMaxDynamicSharedMemorySize, 73728);

    dim3 gp(D_/128, M_/128);   // (8, 64)
    gemm_tc3<true,true><<<gp,128,3*STG_*2>>>(rqh, rql, wph + 0*WSZ, wpl + 0*WSZ,
        bq, g1, be1, mm1, mv1, nullptr, qh, ql);
    gemm_tc3<true,true><<<gp,128,3*STG_*2>>>(rkh, rkl, wph + 1*WSZ, wpl + 1*WSZ,
        bk, g2, be2, mm2, mv2, nullptr, kh, kl);
    gemm_tc3<true,true><<<gp,128,3*STG_*2>>>(rvh, rvl, wph + 2*WSZ, wpl + 2*WSZ,
        bv, g3, be3, mm3, mv3, nullptr, vh, vl);

    scores_tc<<<dim3(8,8,128),256,73728>>>(mask, attn);

    pv_fused<<<dim3(8,128),256>>>(attn);

    gemm_tc3<false,false><<<gp,128,3*STG_*2>>>(ch, cl, wph + 3*WSZ, wpl + 3*WSZ,
        bo, nullptr, nullptr, nullptr, nullptr, out, nullptr, nullptr);
}